// round 3
// baseline (speedup 1.0000x reference)
#include <cuda_runtime.h>
#include <cuda_bf16.h>
#include <math.h>

// Problem constants (fixed shapes per reference)
#define NN 100000
#define EE 3200000
#define IN_DIM 512
#define H1 64
#define H2 32
#define H3 16
#define OUTD 40
#define BN_EPS 1e-5f

// ---------------- scratch (device globals: allocation-free) ----------------
__device__ float g_sup1[NN * H1];
__device__ float g_h1  [NN * H1];
__device__ float g_sup2[NN * H2];
__device__ float g_h2  [NN * H2];
__device__ float g_sup3[NN * H3];
__device__ float g_h3  [NN * H3];
__device__ float g_sup4[NN * OUTD];
__device__ int   g_rowptr[NN + 1];
__device__ float g_stats[128];   // [0..63]=sum, [64..127]=sumsq

// ---------------- f32x2 packed helpers (Blackwell dual-rate fp32) ----------------
__device__ __forceinline__ unsigned long long pack2_dup(float v) {
    unsigned long long r;
    asm("mov.b64 %0, {%1, %1};" : "=l"(r) : "f"(v));
    return r;
}
__device__ __forceinline__ unsigned long long fma2(unsigned long long a,
                                                   unsigned long long b,
                                                   unsigned long long c) {
    unsigned long long d;
    asm("fma.rn.f32x2 %0, %1, %2, %3;" : "=l"(d) : "l"(a), "l"(b), "l"(c));
    return d;
}

// ---------------- CSR build (edge_row is sorted) ----------------
__global__ void build_rowptr_kernel(const int* __restrict__ row, int n, int e) {
    int i = blockIdx.x * blockDim.x + threadIdx.x;
    if (i >= e) return;
    int r = row[i];
    int prev = (i == 0) ? -1 : row[i - 1];
    for (int q = prev + 1; q <= r; q++) g_rowptr[q] = i;
    if (i == e - 1) {
        for (int q = r + 1; q <= n; q++) g_rowptr[q] = e;
    }
}

// ---------------- big GEMM: C[n x 64] = A[n x 512] @ B[512 x 64] ----------------
// BM=128, BN=64, BK=16, 256 threads, 8x4 micro-tile, packed f32x2 FMA.
// A is stored in smem as DUPLICATED pairs (a,a) so the inner loop needs no movs:
//   acc(i, j01) = fma.f32x2( dup(a_i), (b_j, b_j+1), acc )
__global__ __launch_bounds__(256) void gemm512x64_kernel(
    const float* __restrict__ A, const float* __restrict__ B,
    float* __restrict__ C, int n)
{
    __shared__ __align__(16) unsigned long long Asd[16][128]; // 16 KB, dup pairs
    __shared__ __align__(16) float Bs[16][64];                // 4 KB

    int tid = threadIdx.x;
    int tx = tid & 15;        // 0..15 -> col group (4 cols)
    int ty = tid >> 4;        // 0..15 -> row group (8 rows)
    int rowBase = blockIdx.x * 128;

    int lr = tid >> 1;        // 0..127 A-load row
    int lk = (tid & 1) * 8;   // 0 or 8  A-load k offset
    int bkk = tid >> 4;       // 0..15  B-load k
    int bj  = (tid & 15) * 4; // B-load col (float4)

    unsigned long long acc[8][2];
    #pragma unroll
    for (int i = 0; i < 8; i++) { acc[i][0] = 0ULL; acc[i][1] = 0ULL; }

    const float* Arow = A + (size_t)(rowBase + lr) * IN_DIM;
    bool arow_ok = (rowBase + lr) < n;

    for (int k0 = 0; k0 < IN_DIM; k0 += 16) {
        float4 v0 = make_float4(0.f, 0.f, 0.f, 0.f), v1 = v0;
        if (arow_ok) {
            v0 = *reinterpret_cast<const float4*>(Arow + k0 + lk);
            v1 = *reinterpret_cast<const float4*>(Arow + k0 + lk + 4);
        }
        Asd[lk + 0][lr] = pack2_dup(v0.x);
        Asd[lk + 1][lr] = pack2_dup(v0.y);
        Asd[lk + 2][lr] = pack2_dup(v0.z);
        Asd[lk + 3][lr] = pack2_dup(v0.w);
        Asd[lk + 4][lr] = pack2_dup(v1.x);
        Asd[lk + 5][lr] = pack2_dup(v1.y);
        Asd[lk + 6][lr] = pack2_dup(v1.z);
        Asd[lk + 7][lr] = pack2_dup(v1.w);

        float4 vb = *reinterpret_cast<const float4*>(B + (size_t)(k0 + bkk) * 64 + bj);
        *reinterpret_cast<float4*>(&Bs[bkk][bj]) = vb;
        __syncthreads();

        #pragma unroll
        for (int kk = 0; kk < 16; kk++) {
            unsigned long long a[8];
            *reinterpret_cast<ulonglong2*>(&a[0]) = *reinterpret_cast<const ulonglong2*>(&Asd[kk][ty * 8 + 0]);
            *reinterpret_cast<ulonglong2*>(&a[2]) = *reinterpret_cast<const ulonglong2*>(&Asd[kk][ty * 8 + 2]);
            *reinterpret_cast<ulonglong2*>(&a[4]) = *reinterpret_cast<const ulonglong2*>(&Asd[kk][ty * 8 + 4]);
            *reinterpret_cast<ulonglong2*>(&a[6]) = *reinterpret_cast<const ulonglong2*>(&Asd[kk][ty * 8 + 6]);
            ulonglong2 b = *reinterpret_cast<const ulonglong2*>(&Bs[kk][tx * 4]);
            #pragma unroll
            for (int i = 0; i < 8; i++) {
                acc[i][0] = fma2(a[i], b.x, acc[i][0]);
                acc[i][1] = fma2(a[i], b.y, acc[i][1]);
            }
        }
        __syncthreads();
    }

    #pragma unroll
    for (int i = 0; i < 8; i++) {
        int grow = rowBase + ty * 8 + i;
        if (grow < n) {
            ulonglong2 st; st.x = acc[i][0]; st.y = acc[i][1];
            *reinterpret_cast<ulonglong2*>(C + (size_t)grow * 64 + tx * 4) = st;
        }
    }
}

// ---------------- small GEMM: C[n x M] = A[n x K] @ B[K x M] ----------------
template <int K, int M>
__global__ __launch_bounds__(256) void gemm_small_kernel(
    const float* __restrict__ A, const float* __restrict__ B,
    float* __restrict__ C, int n)
{
    __shared__ float sW[K * (M + 1)];
    for (int i = threadIdx.x; i < K * M; i += blockDim.x)
        sW[(i / M) * (M + 1) + (i % M)] = B[i];
    __syncthreads();

    int t = blockIdx.x * blockDim.x + threadIdx.x;
    int row = t / M;
    int colm = t - row * M;
    if (row >= n) return;

    const float* a = A + (size_t)row * K;
    float acc = 0.f;
    #pragma unroll 16
    for (int k = 0; k < K; k++)
        acc += __ldg(a + k) * sW[k * (M + 1) + colm];
    C[(size_t)row * M + colm] = acc;
}

// ---------------- SpMM: out[i] = sum_{e in row i} val[e] * sup[col[e]] ----------------
template <int F>
__global__ __launch_bounds__(256) void spmm_kernel(
    const float* __restrict__ sup, const int* __restrict__ col,
    const float* __restrict__ val, float* __restrict__ out, int n)
{
    if constexpr (F == 64) {
        int gw = (blockIdx.x * blockDim.x + threadIdx.x) >> 5;
        int lane = threadIdx.x & 31;
        if (gw >= n) return;
        int e = g_rowptr[gw], eend = g_rowptr[gw + 1];
        float2 acc = make_float2(0.f, 0.f);
        const float2* s2 = reinterpret_cast<const float2*>(sup);
        #pragma unroll 4
        for (; e < eend; e++) {
            int   c = __ldg(col + e);
            float v = __ldg(val + e);
            float2 sv = __ldg(s2 + (size_t)c * 32 + lane);
            acc.x += v * sv.x;
            acc.y += v * sv.y;
        }
        reinterpret_cast<float2*>(out)[(size_t)gw * 32 + lane] = acc;
    } else if constexpr (F == 32) {
        int gw = (blockIdx.x * blockDim.x + threadIdx.x) >> 5;
        int lane = threadIdx.x & 31;
        if (gw >= n) return;
        int e = g_rowptr[gw], eend = g_rowptr[gw + 1];
        float acc = 0.f;
        #pragma unroll 4
        for (; e < eend; e++) {
            int   c = __ldg(col + e);
            float v = __ldg(val + e);
            acc += v * __ldg(sup + (size_t)c * 32 + lane);
        }
        out[(size_t)gw * 32 + lane] = acc;
    } else {  // F == 16, sub-warps of 16
        int gs = (blockIdx.x * blockDim.x + threadIdx.x) >> 4;
        int lane = threadIdx.x & 15;
        if (gs >= n) return;
        int e = g_rowptr[gs], eend = g_rowptr[gs + 1];
        float acc = 0.f;
        #pragma unroll 4
        for (; e < eend; e++) {
            int   c = __ldg(col + e);
            float v = __ldg(val + e);
            acc += v * __ldg(sup + (size_t)c * 16 + lane);
        }
        out[(size_t)gs * 16 + lane] = acc;
    }
}

// ---------------- final SpMM (F=40) fused with log_softmax -> d_out ----------------
__global__ __launch_bounds__(256) void spmm40_logsoftmax_kernel(
    const float* __restrict__ sup, const int* __restrict__ col,
    const float* __restrict__ val, float* __restrict__ out, int n)
{
    int gw = (blockIdx.x * blockDim.x + threadIdx.x) >> 5;
    int lane = threadIdx.x & 31;
    if (gw >= n) return;
    int e = g_rowptr[gw], eend = g_rowptr[gw + 1];
    bool second = (lane < 8);
    float a0 = 0.f, a1 = 0.f;
    #pragma unroll 2
    for (; e < eend; e++) {
        int   c = __ldg(col + e);
        float v = __ldg(val + e);
        a0 += v * __ldg(sup + (size_t)c * 40 + lane);
        if (second) a1 += v * __ldg(sup + (size_t)c * 40 + 32 + lane);
    }
    float m = a0;
    if (second) m = fmaxf(m, a1);
    #pragma unroll
    for (int off = 16; off > 0; off >>= 1)
        m = fmaxf(m, __shfl_xor_sync(0xffffffffu, m, off));
    float s = __expf(a0 - m);
    if (second) s += __expf(a1 - m);
    #pragma unroll
    for (int off = 16; off > 0; off >>= 1)
        s += __shfl_xor_sync(0xffffffffu, s, off);
    float lse = m + logf(s);
    out[(size_t)gw * 40 + lane] = a0 - lse;
    if (second) out[(size_t)gw * 40 + 32 + lane] = a1 - lse;
}

// ---------------- BN stats: sum & sumsq per feature ----------------
__global__ void zero_stats_kernel() {
    if (threadIdx.x < 128) g_stats[threadIdx.x] = 0.f;
}

template <int F>
__global__ __launch_bounds__(256) void bn_stats_kernel(const float* __restrict__ h, int n) {
    __shared__ float sm[512];
    int f = threadIdx.x % F;
    int rpb = 256 / F;
    int r = blockIdx.x * rpb + threadIdx.x / F;
    int stride = gridDim.x * rpb;
    float s = 0.f, ss = 0.f;
    for (; r < n; r += stride) {
        float v = h[(size_t)r * F + f];
        s += v;
        ss += v * v;
    }
    sm[threadIdx.x] = s;
    sm[256 + threadIdx.x] = ss;
    __syncthreads();
    for (int off = 128; off >= F; off >>= 1) {
        if (threadIdx.x < off) {
            sm[threadIdx.x]       += sm[threadIdx.x + off];
            sm[256 + threadIdx.x] += sm[256 + threadIdx.x + off];
        }
        __syncthreads();
    }
    if (threadIdx.x < F) {
        atomicAdd(&g_stats[threadIdx.x],      sm[threadIdx.x]);
        atomicAdd(&g_stats[64 + threadIdx.x], sm[256 + threadIdx.x]);
    }
}

// ---------------- BN apply + ELU (in place) ----------------
template <int F>
__global__ __launch_bounds__(256) void bn_elu_kernel(
    float* __restrict__ h, const float* __restrict__ gamma,
    const float* __restrict__ beta, int n)
{
    size_t total = (size_t)n * F;
    size_t idx = (size_t)blockIdx.x * blockDim.x + threadIdx.x;
    if (idx >= total) return;
    int f = (int)(idx % F);
    float invN = 1.f / (float)n;
    float mean = g_stats[f] * invN;
    float var  = g_stats[64 + f] * invN - mean * mean;
    float inv  = rsqrtf(var + BN_EPS);
    float v = (h[idx] - mean) * inv * __ldg(gamma + f) + __ldg(beta + f);
    h[idx] = (v > 0.f) ? v : expm1f(v);
}

// ---------------- launch ----------------
extern "C" void kernel_launch(void* const* d_in, const int* in_sizes, int n_in,
                              void* d_out, int out_size) {
    const float* x        = (const float*)d_in[0];
    const int*   edge_row = (const int*)  d_in[1];
    const int*   edge_col = (const int*)  d_in[2];
    const float* edge_val = (const float*)d_in[3];
    const float* W1 = (const float*)d_in[4];
    const float* W2 = (const float*)d_in[5];
    const float* W3 = (const float*)d_in[6];
    const float* W4 = (const float*)d_in[7];
    const float* g1 = (const float*)d_in[8];
    const float* b1 = (const float*)d_in[9];
    const float* g2 = (const float*)d_in[10];
    const float* b2 = (const float*)d_in[11];
    const float* g3 = (const float*)d_in[12];
    const float* b3 = (const float*)d_in[13];
    float* out = (float*)d_out;

    int n = in_sizes[0] / IN_DIM;   // 100000
    int e = in_sizes[1];            // 3200000

    float* sup1; cudaGetSymbolAddress((void**)&sup1, g_sup1);
    float* h1;   cudaGetSymbolAddress((void**)&h1,   g_h1);
    float* sup2; cudaGetSymbolAddress((void**)&sup2, g_sup2);
    float* h2;   cudaGetSymbolAddress((void**)&h2,   g_h2);
    float* sup3; cudaGetSymbolAddress((void**)&sup3, g_sup3);
    float* h3;   cudaGetSymbolAddress((void**)&h3,   g_h3);
    float* sup4; cudaGetSymbolAddress((void**)&sup4, g_sup4);

    // CSR row pointers from sorted edge_row
    build_rowptr_kernel<<<(e + 255) / 256, 256>>>(edge_row, n, e);

    // ---- layer 1 ----
    gemm512x64_kernel<<<(n + 127) / 128, 256>>>(x, W1, sup1, n);
    spmm_kernel<64><<<((size_t)n * 32 + 255) / 256, 256>>>(sup1, edge_col, edge_val, h1, n);
    zero_stats_kernel<<<1, 128>>>();
    bn_stats_kernel<64><<<240, 256>>>(h1, n);
    bn_elu_kernel<64><<<((size_t)n * 64 + 255) / 256, 256>>>(h1, g1, b1, n);

    // ---- layer 2 ----
    gemm_small_kernel<64, 32><<<((size_t)n * 32 + 255) / 256, 256>>>(h1, W2, sup2, n);
    spmm_kernel<32><<<((size_t)n * 32 + 255) / 256, 256>>>(sup2, edge_col, edge_val, h2, n);
    zero_stats_kernel<<<1, 128>>>();
    bn_stats_kernel<32><<<240, 256>>>(h2, n);
    bn_elu_kernel<32><<<((size_t)n * 32 + 255) / 256, 256>>>(h2, g2, b2, n);

    // ---- layer 3 ----
    gemm_small_kernel<32, 16><<<((size_t)n * 16 + 255) / 256, 256>>>(h2, W3, sup3, n);
    spmm_kernel<16><<<((size_t)n * 16 + 255) / 256, 256>>>(sup3, edge_col, edge_val, h3, n);
    zero_stats_kernel<<<1, 128>>>();
    bn_stats_kernel<16><<<240, 256>>>(h3, n);
    bn_elu_kernel<16><<<((size_t)n * 16 + 255) / 256, 256>>>(h3, g3, b3, n);

    // ---- layer 4 + log_softmax ----
    gemm_small_kernel<16, 40><<<((size_t)n * 40 + 255) / 256, 256>>>(h3, W4, sup4, n);
    spmm40_logsoftmax_kernel<<<((size_t)n * 32 + 255) / 256, 256>>>(sup4, edge_col, edge_val, out, n);
}

// round 6
// speedup vs baseline: 1.1196x; 1.1196x over previous
#include <cuda_runtime.h>
#include <cuda_bf16.h>
#include <math.h>

#define NN 100000
#define EE 3200000
#define IN_DIM 512
#define H1 64
#define H2 32
#define H3 16
#define OUTD 40
#define BN_EPS 1e-5f

// ---------------- scratch (device globals: allocation-free) ----------------
__device__ float g_sup1[NN * H1];
__device__ float g_h1  [NN * H1];
__device__ float g_sup2[NN * H2];
__device__ float g_h2  [NN * H2];
__device__ float g_sup3[NN * H3];
__device__ float g_h3  [NN * H3];
__device__ float g_sup4[NN * OUTD];
__device__ int   g_rowptr[NN + 1];
// three stat regions: A(+0), B(+128), C(+256); within a region: sum[f], sumsq at [64+f]
__device__ float g_stats[384];

// ---------------- setup: zero stats + CSR rowptr (edge_row sorted) ----------------
__global__ void setup_kernel(const int* __restrict__ row, int n, int e) {
    // FIX: cover all 384 stats entries (blockDim is 256 -> use first two blocks)
    int z = blockIdx.x * blockDim.x + threadIdx.x;
    if (z < 384) g_stats[z] = 0.f;
    int i = z;
    if (i >= e) return;
    int r = row[i];
    int prev = (i == 0) ? -1 : row[i - 1];
    for (int q = prev + 1; q <= r; q++) g_rowptr[q] = i;
    if (i == e - 1) {
        for (int q = r + 1; q <= n; q++) g_rowptr[q] = e;
    }
}

// ---------------- big GEMM: C[n x 64] = A[n x 512] @ B[512 x 64] ----------------
// BM=64, BN=64, BK=32, 256 threads, 4x4 micro-tile (fp32 FFMA roofline).
__global__ __launch_bounds__(256) void gemm512x64_kernel(
    const float* __restrict__ A, const float* __restrict__ B,
    float* __restrict__ C, int n)
{
    __shared__ __align__(16) float As[32][68];
    __shared__ __align__(16) float Bs[32][64];

    int tid = threadIdx.x;
    int tx = tid & 15;
    int ty = tid >> 4;
    int rowBase = blockIdx.x * 64;

    int ar  = tid >> 3;
    int ac4 = tid & 7;
    int bk  = tid >> 4;
    int bn4 = tid & 15;

    float acc[4][4] = {};

    for (int k0 = 0; k0 < IN_DIM; k0 += 32) {
        #pragma unroll
        for (int rr = 0; rr < 2; rr++) {
            int r = ar + rr * 32;
            int grow = rowBase + r;
            float4 v = make_float4(0.f, 0.f, 0.f, 0.f);
            if (grow < n)
                v = *reinterpret_cast<const float4*>(A + (size_t)grow * IN_DIM + k0 + ac4 * 4);
            As[ac4 * 4 + 0][r] = v.x;
            As[ac4 * 4 + 1][r] = v.y;
            As[ac4 * 4 + 2][r] = v.z;
            As[ac4 * 4 + 3][r] = v.w;
        }
        #pragma unroll
        for (int kk2 = 0; kk2 < 2; kk2++) {
            int k = bk + kk2 * 16;
            float4 v = *reinterpret_cast<const float4*>(B + (size_t)(k0 + k) * 64 + bn4 * 4);
            *reinterpret_cast<float4*>(&Bs[k][bn4 * 4]) = v;
        }
        __syncthreads();

        #pragma unroll
        for (int kk = 0; kk < 32; kk++) {
            float a[4], b[4];
            *reinterpret_cast<float4*>(a) = *reinterpret_cast<const float4*>(&As[kk][ty * 4]);
            *reinterpret_cast<float4*>(b) = *reinterpret_cast<const float4*>(&Bs[kk][tx * 4]);
            #pragma unroll
            for (int i = 0; i < 4; i++)
                #pragma unroll
                for (int j = 0; j < 4; j++)
                    acc[i][j] += a[i] * b[j];
        }
        __syncthreads();
    }

    #pragma unroll
    for (int i = 0; i < 4; i++) {
        int grow = rowBase + ty * 4 + i;
        if (grow < n) {
            *reinterpret_cast<float4*>(C + (size_t)grow * 64 + tx * 4) =
                make_float4(acc[i][0], acc[i][1], acc[i][2], acc[i][3]);
        }
    }
}

// ---------------- persistent SpMM fused with BN-stats accumulation ----------------
template <int F>
__global__ __launch_bounds__(256) void spmm_stats_kernel(
    const float* __restrict__ sup, const int* __restrict__ col,
    const float* __restrict__ val, float* __restrict__ out,
    float* __restrict__ stats, int n)
{
    int wid  = threadIdx.x >> 5;
    int lane = threadIdx.x & 31;

    if constexpr (F == 64) {
        __shared__ float sm[8][64];
        const float2* s2 = reinterpret_cast<const float2*>(sup);
        float2* o2 = reinterpret_cast<float2*>(out);
        float sx = 0.f, sy = 0.f, qx = 0.f, qy = 0.f;
        for (int r = blockIdx.x * 8 + wid; r < n; r += gridDim.x * 8) {
            int e = g_rowptr[r], eend = g_rowptr[r + 1];
            float2 acc = make_float2(0.f, 0.f);
            #pragma unroll 4
            for (; e < eend; e++) {
                int   c = __ldg(col + e);
                float v = __ldg(val + e);
                float2 sv = __ldg(s2 + (size_t)c * 32 + lane);
                acc.x += v * sv.x;
                acc.y += v * sv.y;
            }
            o2[(size_t)r * 32 + lane] = acc;
            sx += acc.x; sy += acc.y;
            qx += acc.x * acc.x; qy += acc.y * acc.y;
        }
        sm[wid][2 * lane] = sx; sm[wid][2 * lane + 1] = sy;
        __syncthreads();
        if (threadIdx.x < 64) {
            float s = 0.f;
            #pragma unroll
            for (int w = 0; w < 8; w++) s += sm[w][threadIdx.x];
            atomicAdd(&stats[threadIdx.x], s);
        }
        __syncthreads();
        sm[wid][2 * lane] = qx; sm[wid][2 * lane + 1] = qy;
        __syncthreads();
        if (threadIdx.x < 64) {
            float s = 0.f;
            #pragma unroll
            for (int w = 0; w < 8; w++) s += sm[w][threadIdx.x];
            atomicAdd(&stats[64 + threadIdx.x], s);
        }
    } else if constexpr (F == 32) {
        __shared__ float sm[8][32];
        float sx = 0.f, qx = 0.f;
        for (int r = blockIdx.x * 8 + wid; r < n; r += gridDim.x * 8) {
            int e = g_rowptr[r], eend = g_rowptr[r + 1];
            float acc = 0.f;
            #pragma unroll 4
            for (; e < eend; e++) {
                int   c = __ldg(col + e);
                float v = __ldg(val + e);
                acc += v * __ldg(sup + (size_t)c * 32 + lane);
            }
            out[(size_t)r * 32 + lane] = acc;
            sx += acc; qx += acc * acc;
        }
        sm[wid][lane] = sx;
        __syncthreads();
        if (threadIdx.x < 32) {
            float s = 0.f;
            #pragma unroll
            for (int w = 0; w < 8; w++) s += sm[w][threadIdx.x];
            atomicAdd(&stats[threadIdx.x], s);
        }
        __syncthreads();
        sm[wid][lane] = qx;
        __syncthreads();
        if (threadIdx.x < 32) {
            float s = 0.f;
            #pragma unroll
            for (int w = 0; w < 8; w++) s += sm[w][threadIdx.x];
            atomicAdd(&stats[64 + threadIdx.x], s);
        }
    } else {  // F == 16: two rows per warp (half-warps)
        __shared__ float sm[8][32];
        int half = lane >> 4;
        int f    = lane & 15;
        float sx = 0.f, qx = 0.f;
        for (int r = blockIdx.x * 16 + wid * 2 + half; r < n; r += gridDim.x * 16) {
            int e = g_rowptr[r], eend = g_rowptr[r + 1];
            float acc = 0.f;
            #pragma unroll 4
            for (; e < eend; e++) {
                int   c = __ldg(col + e);
                float v = __ldg(val + e);
                acc += v * __ldg(sup + (size_t)c * 16 + f);
            }
            out[(size_t)r * 16 + f] = acc;
            sx += acc; qx += acc * acc;
        }
        sm[wid][lane] = sx;
        __syncthreads();
        if (threadIdx.x < 16) {
            float s = 0.f;
            #pragma unroll
            for (int w = 0; w < 8; w++) s += sm[w][threadIdx.x] + sm[w][threadIdx.x + 16];
            atomicAdd(&stats[threadIdx.x], s);
        }
        __syncthreads();
        sm[wid][lane] = qx;
        __syncthreads();
        if (threadIdx.x < 16) {
            float s = 0.f;
            #pragma unroll
            for (int w = 0; w < 8; w++) s += sm[w][threadIdx.x] + sm[w][threadIdx.x + 16];
            atomicAdd(&stats[64 + threadIdx.x], s);
        }
    }
}

// ---------------- fused BN+ELU+GEMM: C[n x M] = elu(bn(A)) @ W  (row per thread) ----------------
template <int K, int M>
__global__ __launch_bounds__(256) void bn_gemm_kernel(
    const float* __restrict__ A, const float* __restrict__ stats,
    const float* __restrict__ gamma, const float* __restrict__ beta,
    const float* __restrict__ W, float* __restrict__ C, int n)
{
    __shared__ float sW[K * M];
    __shared__ float sScale[K], sShift[K];

    for (int i = threadIdx.x; i < K * M; i += blockDim.x) sW[i] = W[i];
    if (threadIdx.x < K) {
        int f = threadIdx.x;
        float invN = 1.f / (float)n;
        float mean = stats[f] * invN;
        float var  = stats[64 + f] * invN - mean * mean;
        float inv  = rsqrtf(var + BN_EPS);
        float sc = inv * gamma[f];
        sScale[f] = sc;
        sShift[f] = beta[f] - mean * sc;
    }
    __syncthreads();

    int r = blockIdx.x * blockDim.x + threadIdx.x;
    if (r >= n) return;

    const float4* a4 = reinterpret_cast<const float4*>(A + (size_t)r * K);
    float acc[M];
    #pragma unroll
    for (int m = 0; m < M; m++) acc[m] = 0.f;

    #pragma unroll
    for (int kc = 0; kc < K / 4; kc++) {
        float4 v = __ldg(a4 + kc);
        float a[4] = {v.x, v.y, v.z, v.w};
        #pragma unroll
        for (int j = 0; j < 4; j++) {
            int k = kc * 4 + j;
            float t = a[j] * sScale[k] + sShift[k];
            t = (t > 0.f) ? t : expm1f(t);
            #pragma unroll
            for (int m = 0; m < M; m++)
                acc[m] += t * sW[k * M + m];
        }
    }

    float4* c4 = reinterpret_cast<float4*>(C + (size_t)r * M);
    #pragma unroll
    for (int m = 0; m < M / 4; m++)
        c4[m] = make_float4(acc[4 * m], acc[4 * m + 1], acc[4 * m + 2], acc[4 * m + 3]);
}

// ---------------- final SpMM (F=40) fused with log_softmax -> d_out ----------------
__global__ __launch_bounds__(256) void spmm40_logsoftmax_kernel(
    const float* __restrict__ sup, const int* __restrict__ col,
    const float* __restrict__ val, float* __restrict__ out, int n)
{
    int gw = (blockIdx.x * blockDim.x + threadIdx.x) >> 5;
    int lane = threadIdx.x & 31;
    if (gw >= n) return;
    int e = g_rowptr[gw], eend = g_rowptr[gw + 1];
    bool second = (lane < 8);
    float a0 = 0.f, a1 = 0.f;
    #pragma unroll 2
    for (; e < eend; e++) {
        int   c = __ldg(col + e);
        float v = __ldg(val + e);
        a0 += v * __ldg(sup + (size_t)c * 40 + lane);
        if (second) a1 += v * __ldg(sup + (size_t)c * 40 + 32 + lane);
    }
    float m = a0;
    if (second) m = fmaxf(m, a1);
    #pragma unroll
    for (int off = 16; off > 0; off >>= 1)
        m = fmaxf(m, __shfl_xor_sync(0xffffffffu, m, off));
    float s = __expf(a0 - m);
    if (second) s += __expf(a1 - m);
    #pragma unroll
    for (int off = 16; off > 0; off >>= 1)
        s += __shfl_xor_sync(0xffffffffu, s, off);
    float lse = m + logf(s);
    out[(size_t)gw * 40 + lane] = a0 - lse;
    if (second) out[(size_t)gw * 40 + 32 + lane] = a1 - lse;
}

// ---------------- launch ----------------
extern "C" void kernel_launch(void* const* d_in, const int* in_sizes, int n_in,
                              void* d_out, int out_size) {
    const float* x        = (const float*)d_in[0];
    const int*   edge_row = (const int*)  d_in[1];
    const int*   edge_col = (const int*)  d_in[2];
    const float* edge_val = (const float*)d_in[3];
    const float* W1 = (const float*)d_in[4];
    const float* W2 = (const float*)d_in[5];
    const float* W3 = (const float*)d_in[6];
    const float* W4 = (const float*)d_in[7];
    const float* g1 = (const float*)d_in[8];
    const float* b1 = (const float*)d_in[9];
    const float* g2 = (const float*)d_in[10];
    const float* b2 = (const float*)d_in[11];
    const float* g3 = (const float*)d_in[12];
    const float* b3 = (const float*)d_in[13];
    float* out = (float*)d_out;

    int n = in_sizes[0] / IN_DIM;   // 100000
    int e = in_sizes[1];            // 3200000

    float* sup1; cudaGetSymbolAddress((void**)&sup1, g_sup1);
    float* h1;   cudaGetSymbolAddress((void**)&h1,   g_h1);
    float* sup2; cudaGetSymbolAddress((void**)&sup2, g_sup2);
    float* h2;   cudaGetSymbolAddress((void**)&h2,   g_h2);
    float* sup3; cudaGetSymbolAddress((void**)&sup3, g_sup3);
    float* h3;   cudaGetSymbolAddress((void**)&h3,   g_h3);
    float* sup4; cudaGetSymbolAddress((void**)&sup4, g_sup4);
    float* stats; cudaGetSymbolAddress((void**)&stats, g_stats);
    float* stA = stats, *stB = stats + 128, *stC = stats + 256;

    const int SPMM_GRID = 592;  // 4 blocks/SM

    // 1: rowptr + zero stats
    setup_kernel<<<(e + 255) / 256, 256>>>(edge_row, n, e);
    // 2: layer-1 dense GEMM
    gemm512x64_kernel<<<(n + 63) / 64, 256>>>(x, W1, sup1, n);
    // 3: SpMM(64) + stats A
    spmm_stats_kernel<64><<<SPMM_GRID, 256>>>(sup1, edge_col, edge_val, h1, stA, n);
    // 4: bn_elu(A) + GEMM 64->32
    bn_gemm_kernel<64, 32><<<(n + 255) / 256, 256>>>(h1, stA, g1, b1, W2, sup2, n);
    // 5: SpMM(32) + stats B
    spmm_stats_kernel<32><<<SPMM_GRID, 256>>>(sup2, edge_col, edge_val, h2, stB, n);
    // 6: bn_elu(B) + GEMM 32->16
    bn_gemm_kernel<32, 16><<<(n + 255) / 256, 256>>>(h2, stB, g2, b2, W3, sup3, n);
    // 7: SpMM(16) + stats C
    spmm_stats_kernel<16><<<SPMM_GRID, 256>>>(sup3, edge_col, edge_val, h3, stC, n);
    // 8: bn_elu(C) + GEMM 16->40
    bn_gemm_kernel<16, 40><<<(n + 255) / 256, 256>>>(h3, stC, g3, b3, W4, sup4, n);
    // 9: SpMM(40) + log_softmax
    spmm40_logsoftmax_kernel<<<((size_t)n * 32 + 255) / 256, 256>>>(sup4, edge_col, edge_val, out, n);
}